// round 6
// baseline (speedup 1.0000x reference)
#include <cuda_runtime.h>
#include <cuda_fp16.h>
#include <cstdint>

#define DDIM  256
#define B_MAX 4096
#define MT    64            // rows per tile
#define AS_STRIDE 264       // halfs per As row
#define AS_U32    132

__device__ float g_num[B_MAX * DDIM];
__device__ float g_den[B_MAX];

// smem layout (bytes):
//   Wt   half 256x264 @ 0        135168
//   As   half  64x264 @ 135168    33792
//   b1s  f32   256    @ 168960     1024
//   w2s  f32   256    @ 169984     1024
//   red  f32    64    @ 171008      256
//   wexp f32    64    @ 171264      256
//   bids i32    64    @ 171520      256
#define SMEM_BYTES 171776

__device__ __forceinline__ float tanh_fast(float v) {
    float e = __expf(2.0f * v);
    return 1.0f - __fdividef(2.0f, 1.0f + e);
}

__device__ __forceinline__ int batch_at(const int* b32, int i, bool is64) {
    return is64 ? b32[2 * i] : b32[i];   // little-endian lower word
}

__global__ __launch_bounds__(512, 1)
void score_pool_kernel(const float* __restrict__ x,
                       const int*   __restrict__ batch32,
                       const float* __restrict__ W1,
                       const float* __restrict__ b1,
                       const float* __restrict__ w2,
                       const float* __restrict__ b2p,
                       int N, int nTiles)
{
    extern __shared__ char smem[];
    __half* Wt   = (__half*)smem;
    __half* As   = (__half*)(smem + 135168);
    float*  b1s  = (float*)(smem + 168960);
    float*  w2s  = (float*)(smem + 169984);
    float*  red  = (float*)(smem + 171008);
    float*  wexp = (float*)(smem + 171264);
    int*    bids = (int*)  (smem + 171520);

    const int tid  = threadIdx.x;
    const int lane = tid & 31;
    const int wid  = tid >> 5;
    const int mw   = wid >> 3;   // 0..1
    const int nw   = wid & 7;    // 0..7

    const bool is64 = (batch32[N - 1] == 0);

    // W1^T -> fp16 smem, once per CTA
    for (int p = tid; p < 256 * 128; p += 512) {
        int n  = p & 255;
        int k2 = p >> 8;
        float f0 = W1[(2 * k2) * 256 + n];
        float f1 = W1[(2 * k2 + 1) * 256 + n];
        *(__half2*)&Wt[n * AS_STRIDE + 2 * k2] = __floats2half2_rn(f0, f1);
    }
    if (tid < 256) { b1s[tid] = b1[tid]; w2s[tid] = w2[tid]; }
    const float b2 = __ldg(b2p);
    __syncthreads();

    const uint32_t* As32 = (const uint32_t*)As;
    const uint32_t* Wt32 = (const uint32_t*)Wt;
    const int arow = mw * 32 + (lane >> 2);
    const int brow = nw * 32 + (lane >> 2);
    const int koff = (lane & 3);
    const int col  = tid & 255;
    const int grp  = tid >> 8;        // 0/1: row half for pooling walk

    // ---- prefetch tile blockIdx.x ----
    float4 pf[8];
    int tile = blockIdx.x;
    {
        int row0 = tile * MT;
        #pragma unroll
        for (int i = 0; i < 8; i++) {
            int f = tid + i * 512;          // 0..4095 over 64 rows x 64 float4
            int r = f >> 6, c4 = f & 63;
            int gr = row0 + r;
            pf[i] = (tile < nTiles && gr < N)
                  ? ((const float4*)x)[(size_t)gr * 64 + c4]
                  : make_float4(0.f, 0.f, 0.f, 0.f);
        }
    }

    for (; tile < nTiles; tile += gridDim.x) {
        const int row0 = tile * MT;

        // ---- convert prefetched regs -> fp16 As ----
        #pragma unroll
        for (int i = 0; i < 8; i++) {
            int f = tid + i * 512;
            int r = f >> 6, c4 = f & 63;
            __half2* dst = (__half2*)&As[r * AS_STRIDE + c4 * 4];
            dst[0] = __floats2half2_rn(pf[i].x, pf[i].y);
            dst[1] = __floats2half2_rn(pf[i].z, pf[i].w);
        }
        if (tid < MT) {
            red[tid] = 0.f;
            int gr = row0 + tid;
            bids[tid] = (gr < N) ? batch_at(batch32, gr, is64) : -1;
        }
        __syncthreads();

        // ---- issue prefetch for next tile (hidden under GEMM) ----
        {
            int nt_ = tile + gridDim.x;
            int nrow0 = nt_ * MT;
            #pragma unroll
            for (int i = 0; i < 8; i++) {
                int f = tid + i * 512;
                int r = f >> 6, c4 = f & 63;
                int gr = nrow0 + r;
                pf[i] = (nt_ < nTiles && gr < N)
                      ? ((const float4*)x)[(size_t)gr * 64 + c4]
                      : make_float4(0.f, 0.f, 0.f, 0.f);
            }
        }

        // ---- GEMM 64 x 256 x 256, warp tile 32x32 ----
        float c[2][4][4];
        #pragma unroll
        for (int t = 0; t < 2; t++)
            #pragma unroll
            for (int nt = 0; nt < 4; nt++)
                #pragma unroll
                for (int q = 0; q < 4; q++) c[t][nt][q] = 0.f;

        #pragma unroll 1
        for (int ks = 0; ks < 16; ks++) {
            const int kb = ks * 8 + koff;
            uint32_t a[2][4];
            #pragma unroll
            for (int t = 0; t < 2; t++) {
                int r = arow + t * 16;
                a[t][0] = As32[r * AS_U32 + kb];
                a[t][1] = As32[(r + 8) * AS_U32 + kb];
                a[t][2] = As32[r * AS_U32 + kb + 4];
                a[t][3] = As32[(r + 8) * AS_U32 + kb + 4];
            }
            #pragma unroll
            for (int nt = 0; nt < 4; nt++) {
                int n = brow + nt * 8;
                uint32_t bb0 = Wt32[n * AS_U32 + kb];
                uint32_t bb1 = Wt32[n * AS_U32 + kb + 4];
                #pragma unroll
                for (int t = 0; t < 2; t++) {
                    asm volatile(
                        "mma.sync.aligned.m16n8k16.row.col.f32.f16.f16.f32 "
                        "{%0,%1,%2,%3}, {%4,%5,%6,%7}, {%8,%9}, {%0,%1,%2,%3};\n"
                        : "+f"(c[t][nt][0]), "+f"(c[t][nt][1]),
                          "+f"(c[t][nt][2]), "+f"(c[t][nt][3])
                        : "r"(a[t][0]), "r"(a[t][1]), "r"(a[t][2]), "r"(a[t][3]),
                          "r"(bb0), "r"(bb1));
                }
            }
        }

        // ---- epilogue: red[row] += sum_j tanh(h+b1)*w2 over this warp's 32 cols ----
        #pragma unroll
        for (int t = 0; t < 2; t++) {
            float p0 = 0.f, p1 = 0.f;
            #pragma unroll
            for (int nt = 0; nt < 4; nt++) {
                int j0 = nw * 32 + nt * 8 + 2 * (lane & 3);
                float bb0 = b1s[j0], bb1 = b1s[j0 + 1];
                float ww0 = w2s[j0], ww1 = w2s[j0 + 1];
                p0 += tanh_fast(c[t][nt][0] + bb0) * ww0 + tanh_fast(c[t][nt][1] + bb1) * ww1;
                p1 += tanh_fast(c[t][nt][2] + bb0) * ww0 + tanh_fast(c[t][nt][3] + bb1) * ww1;
            }
            p0 += __shfl_xor_sync(0xffffffffu, p0, 1);
            p0 += __shfl_xor_sync(0xffffffffu, p0, 2);
            p1 += __shfl_xor_sync(0xffffffffu, p1, 1);
            p1 += __shfl_xor_sync(0xffffffffu, p1, 2);
            if ((lane & 3) == 0) {
                int r0 = mw * 32 + t * 16 + (lane >> 2);
                atomicAdd(&red[r0], p0);
                atomicAdd(&red[r0 + 8], p1);
            }
        }
        __syncthreads();

        // ---- softmax weights (no max needed: |s| <= ~6, exp fp32-safe) ----
        if (tid < MT) {
            int gr = row0 + tid;
            wexp[tid] = (gr < N) ? __expf(red[tid] + b2) : 0.f;
        }
        __syncthreads();

        // ---- pooling walk: per-segment partial sums, flush on boundary ----
        {
            const int rbase = grp * 32;
            float acc = 0.f, dacc = 0.f;
            int cur = bids[rbase];
            #pragma unroll 4
            for (int r = 0; r < 32; r++) {
                int row = rbase + r;
                int seg = bids[row];
                if (seg != cur) {
                    if (cur >= 0) {
                        atomicAdd(&g_num[cur * DDIM + col], acc);
                        if (col == 0) atomicAdd(&g_den[cur], dacc);
                    }
                    acc = 0.f; dacc = 0.f; cur = seg;
                }
                float w  = wexp[row];
                float xv = __half2float(As[row * AS_STRIDE + col]);
                acc += w * xv;
                if (col == 0) dacc += w;
            }
            if (cur >= 0) {
                atomicAdd(&g_num[cur * DDIM + col], acc);
                if (col == 0) atomicAdd(&g_den[cur], dacc);
            }
        }
        __syncthreads();
    }
}

// ---------------- output GEMM: out = (num/den) @ Wp + bp ----------------
__global__ __launch_bounds__(256)
void out_kernel(const float* __restrict__ num,
                const float* __restrict__ den,
                const float* __restrict__ Wp,
                const float* __restrict__ bp,
                float* __restrict__ out)
{
    __shared__ float ps[16][DDIM];
    const int b0  = blockIdx.x * 16;
    const int tid = threadIdx.x;

    for (int p = tid; p < 16 * DDIM; p += 256) {
        int r = p >> 8, c = p & 255;
        float d = den[b0 + r];
        float inv = (d > 0.f) ? 1.0f / d : 0.f;
        ps[r][c] = num[(b0 + r) * DDIM + c] * inv;
    }
    __syncthreads();

    float acc[16];
    #pragma unroll
    for (int r = 0; r < 16; r++) acc[r] = 0.f;

    for (int k = 0; k < DDIM; k++) {
        float w = Wp[k * DDIM + tid];
        #pragma unroll
        for (int r = 0; r < 16; r++) acc[r] += ps[r][k] * w;
    }
    const float bias = bp[tid];
    #pragma unroll
    for (int r = 0; r < 16; r++) out[(b0 + r) * DDIM + tid] = acc[r] + bias;
}

// ---------------- launch ----------------
extern "C" void kernel_launch(void* const* d_in, const int* in_sizes, int n_in,
                              void* d_out, int out_size)
{
    const float* x     = (const float*)d_in[0];
    const int*   batch = (const int*)d_in[1];   // int32 or int64; probed on device
    const float* W1    = (const float*)d_in[2];
    const float* b1    = (const float*)d_in[3];
    const float* w2    = (const float*)d_in[4];
    const float* b2    = (const float*)d_in[5];
    const float* Wp    = (const float*)d_in[6];
    const float* bp    = (const float*)d_in[7];
    float*       out   = (float*)d_out;

    const int N  = in_sizes[0] / DDIM;   // 1,000,000
    const int Bn = out_size / DDIM;      // 4096

    float* d_num; cudaGetSymbolAddress((void**)&d_num, g_num);
    float* d_den; cudaGetSymbolAddress((void**)&d_den, g_den);

    cudaMemsetAsync(d_num, 0, (size_t)Bn * DDIM * sizeof(float));
    cudaMemsetAsync(d_den, 0, (size_t)Bn * sizeof(float));

    const int nTiles = (N + MT - 1) / MT;
    cudaFuncSetAttribute(score_pool_kernel, cudaFuncAttributeMaxDynamicSharedMemorySize, SMEM_BYTES);
    score_pool_kernel<<<152, 512, SMEM_BYTES>>>(x, batch, W1, b1, w2, b2, N, nTiles);
    out_kernel<<<Bn / 16, 256>>>(d_num, d_den, Wp, bp, out);
}

// round 8
// speedup vs baseline: 1.4897x; 1.4897x over previous
#include <cuda_runtime.h>
#include <cuda_fp16.h>
#include <cstdint>

#define DDIM  256
#define B_MAX 4096
#define MT    128
#define AS_STRIDE 264
#define AS_U32    132

__device__ float g_num[B_MAX * DDIM];
__device__ float g_den[B_MAX];

// smem layout (bytes):
//   Wt   half 256x264 @ 0        135168
//   As   half 128x264 @ 135168    67584
//   b1s  f32   256    @ 202752     1024
//   w2s  f32   256    @ 203776     1024
//   red  f32   128    @ 204800      512
//   wexp f32   128    @ 205312      512
//   bids i32   128    @ 205824      512
#define SMEM_BYTES 206336

__device__ __forceinline__ float tanh_fast(float v) {
    float e = __expf(2.0f * v);
    return 1.0f - __fdividef(2.0f, 1.0f + e);
}

__device__ __forceinline__ int batch_at(const int* b32, int i, bool is64) {
    return is64 ? b32[2 * i] : b32[i];   // little-endian lower word
}

__global__ __launch_bounds__(512, 1)
void score_pool_kernel(const float* __restrict__ x,
                       const int*   __restrict__ batch32,
                       const float* __restrict__ W1,
                       const float* __restrict__ b1,
                       const float* __restrict__ w2,
                       const float* __restrict__ b2p,
                       int N, int nTiles)
{
    extern __shared__ char smem[];
    __half* Wt   = (__half*)smem;
    __half* As   = (__half*)(smem + 135168);
    float*  b1s  = (float*)(smem + 202752);
    float*  w2s  = (float*)(smem + 203776);
    float*  red  = (float*)(smem + 204800);
    float*  wexp = (float*)(smem + 205312);
    int*    bids = (int*)  (smem + 205824);

    const int tid  = threadIdx.x;
    const int lane = tid & 31;
    const int wid  = tid >> 5;
    const int mw   = wid >> 2;   // 0..3 (M warp row)
    const int nw   = wid & 3;    // 0..3 (N warp col)

    const bool is64 = (batch32[N - 1] == 0);

    // W1^T -> fp16 smem, once per CTA
    for (int p = tid; p < 256 * 128; p += 512) {
        int n  = p & 255;
        int k2 = p >> 8;
        float f0 = W1[(2 * k2) * 256 + n];
        float f1 = W1[(2 * k2 + 1) * 256 + n];
        *(__half2*)&Wt[n * AS_STRIDE + 2 * k2] = __floats2half2_rn(f0, f1);
    }
    if (tid < 256) { b1s[tid] = b1[tid]; w2s[tid] = w2[tid]; }
    const float b2 = __ldg(b2p);
    __syncthreads();

    const uint32_t* As32 = (const uint32_t*)As;
    const uint32_t* Wt32 = (const uint32_t*)Wt;
    const int arow = mw * 32 + (lane >> 2);
    const int brow = nw * 64 + (lane >> 2);
    const int koff = (lane & 3);
    const int col  = tid & 255;
    const int grp  = tid >> 8;        // 0/1: 64-row half for pooling walk

    for (int tile = blockIdx.x; tile < nTiles; tile += gridDim.x) {
        const int row0 = tile * MT;

        // ---- load 128x256 fp32 X slab -> fp16 smem (zero pad past N) ----
        for (int p = tid; p < 128 * 64; p += 512) {
            int r  = p >> 6;
            int c4 = p & 63;
            int gr = row0 + r;
            float4 v = make_float4(0.f, 0.f, 0.f, 0.f);
            if (gr < N) v = ((const float4*)x)[(size_t)gr * 64 + c4];
            __half2* dst = (__half2*)&As[r * AS_STRIDE + c4 * 4];
            dst[0] = __floats2half2_rn(v.x, v.y);
            dst[1] = __floats2half2_rn(v.z, v.w);
        }
        if (tid < MT) {
            red[tid] = 0.f;
            int gr = row0 + tid;
            bids[tid] = (gr < N) ? batch_at(batch32, gr, is64) : -1;
        }
        __syncthreads();

        // ---- GEMM 128 x 256 x 256, warp tile 32x64 ----
        float c[2][8][4];
        #pragma unroll
        for (int t = 0; t < 2; t++)
            #pragma unroll
            for (int nt = 0; nt < 8; nt++)
                #pragma unroll
                for (int q = 0; q < 4; q++) c[t][nt][q] = 0.f;

        #pragma unroll 1
        for (int ks = 0; ks < 16; ks++) {
            const int kb = ks * 8 + koff;
            uint32_t a[2][4];
            #pragma unroll
            for (int t = 0; t < 2; t++) {
                int r = arow + t * 16;
                a[t][0] = As32[r * AS_U32 + kb];
                a[t][1] = As32[(r + 8) * AS_U32 + kb];
                a[t][2] = As32[r * AS_U32 + kb + 4];
                a[t][3] = As32[(r + 8) * AS_U32 + kb + 4];
            }
            #pragma unroll
            for (int nt = 0; nt < 8; nt++) {
                int n = brow + nt * 8;
                uint32_t bb0 = Wt32[n * AS_U32 + kb];
                uint32_t bb1 = Wt32[n * AS_U32 + kb + 4];
                #pragma unroll
                for (int t = 0; t < 2; t++) {
                    asm volatile(
                        "mma.sync.aligned.m16n8k16.row.col.f32.f16.f16.f32 "
                        "{%0,%1,%2,%3}, {%4,%5,%6,%7}, {%8,%9}, {%0,%1,%2,%3};\n"
                        : "+f"(c[t][nt][0]), "+f"(c[t][nt][1]),
                          "+f"(c[t][nt][2]), "+f"(c[t][nt][3])
                        : "r"(a[t][0]), "r"(a[t][1]), "r"(a[t][2]), "r"(a[t][3]),
                          "r"(bb0), "r"(bb1));
                }
            }
        }

        // ---- epilogue: red[row] += sum_j tanh(h+b1)*w2 ----
        #pragma unroll
        for (int t = 0; t < 2; t++) {
            float p0 = 0.f, p1 = 0.f;
            #pragma unroll
            for (int nt = 0; nt < 8; nt++) {
                int j0 = nw * 64 + nt * 8 + 2 * (lane & 3);
                float bb0 = b1s[j0], bb1 = b1s[j0 + 1];
                float ww0 = w2s[j0], ww1 = w2s[j0 + 1];
                p0 += tanh_fast(c[t][nt][0] + bb0) * ww0 + tanh_fast(c[t][nt][1] + bb1) * ww1;
                p1 += tanh_fast(c[t][nt][2] + bb0) * ww0 + tanh_fast(c[t][nt][3] + bb1) * ww1;
            }
            p0 += __shfl_xor_sync(0xffffffffu, p0, 1);
            p0 += __shfl_xor_sync(0xffffffffu, p0, 2);
            p1 += __shfl_xor_sync(0xffffffffu, p1, 1);
            p1 += __shfl_xor_sync(0xffffffffu, p1, 2);
            if ((lane & 3) == 0) {
                int r0 = mw * 32 + t * 16 + (lane >> 2);
                atomicAdd(&red[r0], p0);
                atomicAdd(&red[r0 + 8], p1);
            }
        }
        __syncthreads();

        // ---- softmax weights (|s| small: fp32 exp safe; identical after norm) ----
        if (tid < MT) {
            int gr = row0 + tid;
            wexp[tid] = (gr < N) ? __expf(red[tid] + b2) : 0.f;
        }
        __syncthreads();

        // ---- pooling walk over resident tile: per-segment partial sums ----
        {
            const int rbase = grp * 64;
            float acc = 0.f, dacc = 0.f;
            int cur = bids[rbase];
            #pragma unroll 4
            for (int r = 0; r < 64; r++) {
                int row = rbase + r;
                int seg = bids[row];
                if (seg != cur) {
                    if (cur >= 0) {
                        atomicAdd(&g_num[cur * DDIM + col], acc);
                        if (col == 0) atomicAdd(&g_den[cur], dacc);
                    }
                    acc = 0.f; dacc = 0.f; cur = seg;
                }
                float w  = wexp[row];
                float xv = __half2float(As[row * AS_STRIDE + col]);
                acc += w * xv;
                if (col == 0) dacc += w;
            }
            if (cur >= 0) {
                atomicAdd(&g_num[cur * DDIM + col], acc);
                if (col == 0) atomicAdd(&g_den[cur], dacc);
            }
        }
        __syncthreads();
    }
}

// ---------------- output GEMM: out = (num/den) @ Wp + bp ----------------
__global__ __launch_bounds__(256)
void out_kernel(const float* __restrict__ num,
                const float* __restrict__ den,
                const float* __restrict__ Wp,
                const float* __restrict__ bp,
                float* __restrict__ out)
{
    __shared__ float ps[16][DDIM];
    const int b0  = blockIdx.x * 16;
    const int tid = threadIdx.x;

    for (int p = tid; p < 16 * DDIM; p += 256) {
        int r = p >> 8, c = p & 255;
        float d = den[b0 + r];
        float inv = (d > 0.f) ? 1.0f / d : 0.f;
        ps[r][c] = num[(b0 + r) * DDIM + c] * inv;
    }
    __syncthreads();

    float acc[16];
    #pragma unroll
    for (int r = 0; r < 16; r++) acc[r] = 0.f;

    // k unrolled by 8: 8 independent LDGs in flight (Wp is L2-resident)
    #pragma unroll 1
    for (int k0 = 0; k0 < DDIM; k0 += 8) {
        float w[8];
        #pragma unroll
        for (int i = 0; i < 8; i++) w[i] = Wp[(k0 + i) * DDIM + tid];
        #pragma unroll
        for (int i = 0; i < 8; i++) {
            float pv;
            #pragma unroll
            for (int r = 0; r < 16; r++) {
                pv = ps[r][k0 + i];
                acc[r] += pv * w[i];
            }
        }
    }
    const float bias = bp[tid];
    #pragma unroll
    for (int r = 0; r < 16; r++) out[(b0 + r) * DDIM + tid] = acc[r] + bias;
}

// ---------------- launch ----------------
extern "C" void kernel_launch(void* const* d_in, const int* in_sizes, int n_in,
                              void* d_out, int out_size)
{
    const float* x     = (const float*)d_in[0];
    const int*   batch = (const int*)d_in[1];   // int32 or int64; probed on device
    const float* W1    = (const float*)d_in[2];
    const float* b1    = (const float*)d_in[3];
    const float* w2    = (const float*)d_in[4];
    const float* b2    = (const float*)d_in[5];
    const float* Wp    = (const float*)d_in[6];
    const float* bp    = (const float*)d_in[7];
    float*       out   = (float*)d_out;

    const int N  = in_sizes[0] / DDIM;   // 1,000,000
    const int Bn = out_size / DDIM;      // 4096

    float* d_num; cudaGetSymbolAddress((void**)&d_num, g_num);
    float* d_den; cudaGetSymbolAddress((void**)&d_den, g_den);

    cudaMemsetAsync(d_num, 0, (size_t)Bn * DDIM * sizeof(float));
    cudaMemsetAsync(d_den, 0, (size_t)Bn * sizeof(float));

    const int nTiles = (N + MT - 1) / MT;
    cudaFuncSetAttribute(score_pool_kernel, cudaFuncAttributeMaxDynamicSharedMemorySize, SMEM_BYTES);
    score_pool_kernel<<<152, 512, SMEM_BYTES>>>(x, batch, W1, b1, w2, b2, N, nTiles);
    out_kernel<<<Bn / 16, 256>>>(d_num, d_den, Wp, bp, out);
}